// round 1
// baseline (speedup 1.0000x reference)
#include <cuda_runtime.h>

#define BB 4
#define CC 4
#define HH 96
#define WW 96
#define HW (HH*WW)
#define GINF 20000   // sentinel "no point in column"; GINF^2 ~ 4e8 fits int32

__device__ unsigned char g_predLab[BB*HW];
__device__ unsigned char g_maskP[BB*HW];
__device__ unsigned char g_maskT[BB*HW];
__device__ int g_gP[BB*HW];
__device__ int g_gT[BB*HW];
__device__ int g_fwd[BB];
__device__ int g_bwd[BB];

__global__ void k_init() {
    int t = threadIdx.x;
    if (t < BB) { g_fwd[t] = -1; g_bwd[t] = -1; }
}

// argmax over channel dim (NCHW), first-max tie-break like jnp.argmax
__global__ void k_argmax(const float* __restrict__ out) {
    int idx = blockIdx.x * blockDim.x + threadIdx.x;
    if (idx >= BB*HW) return;
    int b = idx / HW, p = idx % HW;
    const float* base = out + (size_t)b * CC * HW + p;
    float best = base[0];
    int bi = 0;
#pragma unroll
    for (int c = 1; c < CC; c++) {
        float v = base[(size_t)c * HW];
        if (v > best) { best = v; bi = c; }
    }
    g_predLab[idx] = (unsigned char)bi;
}

// boundary = any 4-neighbor has a different label (equivalent to the
// per-class union in the reference: a differing pair always involves a class>0)
__global__ void k_boundary(const int* __restrict__ tgt) {
    int idx = blockIdx.x * blockDim.x + threadIdx.x;
    if (idx >= BB*HW) return;
    int p = idx % HW;
    int i = p / WW, j = p % WW;

    int lab = g_predLab[idx];
    int mp = 0;
    if (i > 0     && g_predLab[idx - WW] != lab) mp = 1;
    if (i < HH-1  && g_predLab[idx + WW] != lab) mp = 1;
    if (j > 0     && g_predLab[idx - 1 ] != lab) mp = 1;
    if (j < WW-1  && g_predLab[idx + 1 ] != lab) mp = 1;
    g_maskP[idx] = (unsigned char)mp;

    int t = tgt[idx];
    int mt = 0;
    if (i > 0     && tgt[idx - WW] != t) mt = 1;
    if (i < HH-1  && tgt[idx + WW] != t) mt = 1;
    if (j > 0     && tgt[idx - 1 ] != t) mt = 1;
    if (j < WW-1  && tgt[idx + 1 ] != t) mt = 1;
    g_maskT[idx] = (unsigned char)mt;
}

// per-column 1D distance: g[i][j] = min over boundary i' in column j of |i - i'|
// (forward + backward scan). One block per image, one thread per column.
__global__ void k_colpass() {
    int b = blockIdx.x;
    int j = threadIdx.x;
    if (j >= WW) return;
    const unsigned char* mP = g_maskP + b*HW;
    const unsigned char* mT = g_maskT + b*HW;
    int* gP = g_gP + b*HW;
    int* gT = g_gT + b*HW;

    int dP = GINF, dT = GINF;
    for (int i = 0; i < HH; i++) {
        int o = i*WW + j;
        dP = mP[o] ? 0 : min(dP + 1, GINF);
        dT = mT[o] ? 0 : min(dT + 1, GINF);
        gP[o] = dP; gT[o] = dT;
    }
    dP = GINF; dT = GINF;
    for (int i = HH-1; i >= 0; i--) {
        int o = i*WW + j;
        dP = mP[o] ? 0 : min(dP + 1, GINF);
        dT = mT[o] ? 0 : min(dT + 1, GINF);
        gP[o] = min(gP[o], dP);
        gT[o] = min(gT[o], dT);
    }
}

// second EDT pass along rows + directed-Hausdorff max reduction.
// One block per (b, row), one thread per column.
__global__ void k_rowpass() {
    int bi = blockIdx.x;            // 0 .. B*H-1
    int b = bi / HH, i = bi % HH;
    int j = threadIdx.x;

    __shared__ int sqP[WW], sqT[WW];
    __shared__ int redF[WW], redB[WW];

    int base = b*HW + i*WW;
    int gp = g_gP[base + j];
    int gt = g_gT[base + j];
    sqP[j] = gp * gp;
    sqT[j] = gt * gt;
    int mp = g_maskP[base + j];
    int mt = g_maskT[base + j];
    __syncthreads();

    int d2T = 0x7FFFFFFF, d2P = 0x7FFFFFFF;
#pragma unroll 8
    for (int jp = 0; jp < WW; jp++) {
        int dj = j - jp;
        int djs = dj * dj;
        d2T = min(d2T, djs + sqT[jp]);   // distance to target boundary set
        d2P = min(d2P, djs + sqP[jp]);   // distance to pred boundary set
    }

    redF[j] = mp ? d2T : -1;   // fwd: pred points -> target set
    redB[j] = mt ? d2P : -1;   // bwd: target points -> pred set
    __syncthreads();
    for (int s = 64; s > 0; s >>= 1) {
        if (j < s && j + s < WW) {
            redF[j] = max(redF[j], redF[j+s]);
            redB[j] = max(redB[j], redB[j+s]);
        }
        __syncthreads();
    }
    if (j == 0) {
        atomicMax(&g_fwd[b], redF[0]);
        atomicMax(&g_bwd[b], redB[0]);
    }
}

__global__ void k_final(float* __restrict__ out) {
    float sum = 0.0f;
#pragma unroll
    for (int b = 0; b < BB; b++) {
        int v = max(max(g_fwd[b], g_bwd[b]), 0);
        // empty-set sentinel -> reference's sqrt(BIG)=sqrt(1e10)
        float d2 = (v >= 100000000) ? 1e10f : (float)v;
        sum += sqrtf(d2);
    }
    out[0] = sum * (1.0f / BB);
}

extern "C" void kernel_launch(void* const* d_in, const int* in_sizes, int n_in,
                              void* d_out, int out_size) {
    const float* outp = (const float*)d_in[0];   // [B,C,H,W] fp32
    const int*   tgt  = (const int*)d_in[1];     // [B,H,W] int32

    k_init<<<1, 32>>>();
    k_argmax<<<(BB*HW + 255) / 256, 256>>>(outp);
    k_boundary<<<(BB*HW + 255) / 256, 256>>>(tgt);
    k_colpass<<<BB, WW>>>();
    k_rowpass<<<BB*HH, WW>>>();
    k_final<<<1, 1>>>((float*)d_out);
}

// round 2
// speedup vs baseline: 1.8539x; 1.8539x over previous
#include <cuda_runtime.h>

#define BB 4
#define CC 4
#define HH 96
#define WW 96
#define HW (HH*WW)

// global scratch (u8 column distances; g==0 <=> boundary pixel)
__device__ unsigned char g_gP[BB*HW];
__device__ unsigned char g_gT[BB*HW];
__device__ int g_fwd[BB];
__device__ int g_bwd[BB];
__device__ unsigned int g_count;

// ---------------------------------------------------------------------------
// K1: fused argmax + boundary + column EDT (per-image block, all in smem)
// ---------------------------------------------------------------------------
__global__ __launch_bounds__(768, 1)
void k_front(const float* __restrict__ outp, const int* __restrict__ tgt) {
    __shared__ unsigned char labP[HW];
    __shared__ unsigned char labT[HW];
    __shared__ unsigned char sgP[HW];
    __shared__ unsigned char sgT[HW];

    const int b   = blockIdx.x;
    const int tid = threadIdx.x;

    // init reduction state (runs before K2 in stream order)
    if (tid == 0) {
        g_fwd[b] = -1;
        g_bwd[b] = -1;
        if (b == 0) g_count = 0;
    }

    // ---- phase 1: argmax over channels + copy target labels ----
    const float* base = outp + (size_t)b * CC * HW;
    const int*   tb   = tgt + (size_t)b * HW;
    for (int idx = tid; idx < HW; idx += 768) {
        float v0 = base[idx];
        float v1 = base[idx + HW];
        float v2 = base[idx + 2*HW];
        float v3 = base[idx + 3*HW];
        int bi = 0; float best = v0;
        if (v1 > best) { best = v1; bi = 1; }
        if (v2 > best) { best = v2; bi = 2; }
        if (v3 > best) { best = v3; bi = 3; }
        labP[idx] = (unsigned char)bi;
        labT[idx] = (unsigned char)tb[idx];
    }
    __syncthreads();

    // ---- phase 2: boundary masks -> sg = 0 (boundary) / 255 ----
    for (int idx = tid; idx < HW; idx += 768) {
        int i = idx / WW, j = idx % WW;

        int lp = labP[idx];
        int mp = 0;
        if (i > 0    && labP[idx - WW] != lp) mp = 1;
        if (i < HH-1 && labP[idx + WW] != lp) mp = 1;
        if (j > 0    && labP[idx - 1 ] != lp) mp = 1;
        if (j < WW-1 && labP[idx + 1 ] != lp) mp = 1;
        sgP[idx] = mp ? 0 : 255;

        int lt = labT[idx];
        int mt = 0;
        if (i > 0    && labT[idx - WW] != lt) mt = 1;
        if (i < HH-1 && labT[idx + WW] != lt) mt = 1;
        if (j > 0    && labT[idx - 1 ] != lt) mt = 1;
        if (j < WW-1 && labT[idx + 1 ] != lt) mt = 1;
        sgT[idx] = mt ? 0 : 255;
    }
    __syncthreads();

    // ---- phase 3: forward column scan (threads 0..95: P, 96..191: T) ----
    if (tid < 192) {
        unsigned char* sg = (tid < 96) ? sgP : sgT;
        int j = (tid < 96) ? tid : tid - 96;
        int d = 255;
        #pragma unroll 4
        for (int i = 0; i < HH; i++) {
            int o = i*WW + j;
            d = (sg[o] == 0) ? 0 : min(d + 1, 255);
            sg[o] = (unsigned char)d;
        }
    }
    __syncthreads();

    // ---- phase 4: backward column scan, min-combine (g==0 still <=> mask) ----
    if (tid < 192) {
        unsigned char* sg = (tid < 96) ? sgP : sgT;
        int j = (tid < 96) ? tid : tid - 96;
        int d = 255;
        #pragma unroll 4
        for (int i = HH-1; i >= 0; i--) {
            int o = i*WW + j;
            int v = sg[o];
            d = (v == 0) ? 0 : min(d + 1, 255);
            if (d < v) sg[o] = (unsigned char)d;
        }
    }
    __syncthreads();

    // ---- phase 5: dump to global for the row-pass kernel ----
    unsigned char* gP = g_gP + b*HW;
    unsigned char* gT = g_gT + b*HW;
    for (int idx = tid; idx < HW; idx += 768) {
        gP[idx] = sgP[idx];
        gT[idx] = sgT[idx];
    }
}

// ---------------------------------------------------------------------------
// K2: row min-plus pass + directed Hausdorff max + (last block) final mean
// ---------------------------------------------------------------------------
__global__ __launch_bounds__(WW)
void k_row(float* __restrict__ out) {
    const int bi = blockIdx.x;        // 0 .. B*H-1
    const int b  = bi / HH, i = bi % HH;
    const int j  = threadIdx.x;

    __shared__ unsigned char rP[WW];
    __shared__ unsigned char rT[WW];
    __shared__ int redF[WW], redB[WW];

    const int base = b*HW + i*WW;
    const int gp = g_gP[base + j];
    const int gt = g_gT[base + j];
    rP[j] = (unsigned char)gp;
    rT[j] = (unsigned char)gt;
    const int mp = (gp == 0);
    const int mt = (gt == 0);
    __syncthreads();

    int d2T = 0x7FFFFFFF, d2P = 0x7FFFFFFF;
    #pragma unroll 8
    for (int jp = 0; jp < WW; jp++) {
        int dj  = j - jp;
        int djs = dj * dj;
        int a = rT[jp]; d2T = min(d2T, djs + a*a);
        int c = rP[jp]; d2P = min(d2P, djs + c*c);
    }

    redF[j] = mp ? d2T : -1;   // fwd: pred boundary -> target set
    redB[j] = mt ? d2P : -1;   // bwd: target boundary -> pred set
    __syncthreads();
    for (int s = 64; s > 0; s >>= 1) {
        if (j < s && j + s < WW) {
            redF[j] = max(redF[j], redF[j+s]);
            redB[j] = max(redB[j], redB[j+s]);
        }
        __syncthreads();
    }

    if (j == 0) {
        atomicMax(&g_fwd[b], redF[0]);
        atomicMax(&g_bwd[b], redB[0]);
        __threadfence();
        unsigned int ticket = atomicAdd(&g_count, 1u);
        if (ticket == (unsigned)(BB*HH - 1)) {
            __threadfence();
            float sum = 0.0f;
            #pragma unroll
            for (int bb = 0; bb < BB; bb++) {
                int f = atomicMax(&g_fwd[bb], -1);   // atomic read
                int w = atomicMax(&g_bwd[bb], -1);
                int v = max(max(f, w), 0);
                // sentinel (empty boundary set): 255^2=65025 >> real max 18050
                float d2 = (v >= 50000) ? 1e10f : (float)v;
                sum += sqrtf(d2);
            }
            out[0] = sum * (1.0f / BB);
        }
    }
}

extern "C" void kernel_launch(void* const* d_in, const int* in_sizes, int n_in,
                              void* d_out, int out_size) {
    const float* outp = (const float*)d_in[0];   // [B,C,H,W] fp32
    const int*   tgt  = (const int*)d_in[1];     // [B,H,W] int32

    k_front<<<BB, 768>>>(outp, tgt);
    k_row<<<BB*HH, WW>>>((float*)d_out);
}

// round 3
// speedup vs baseline: 2.6136x; 1.4098x over previous
#include <cuda_runtime.h>

#define BB 4
#define CC 4
#define HH 96
#define WW 96
#define HW (HH*WW)
#define NWRD (HW/32)           // 288 mask words
#define NTHR 768
#define NWARP (NTHR/32)

__device__ volatile float g_res[BB];
__device__ unsigned int g_count;   // zero-init at load; reset by last block each launch

__device__ __forceinline__ int getbit(const unsigned* m, int idx) {
    return (m[idx >> 5] >> (idx & 31)) & 1;
}

// vertical nearest-boundary search in column j (idx = i*WW + j). 255 if none.
__device__ __forceinline__ int vsearch(const unsigned* m, int idx, int i) {
    if (getbit(m, idx)) return 0;
    #pragma unroll 1
    for (int r = 1; r < HH; r++) {
        bool any = false;
        if (i - r >= 0) { any = true; if (getbit(m, idx - r*WW)) return r; }
        if (i + r < HH) { any = true; if (getbit(m, idx + r*WW)) return r; }
        if (!any) break;
    }
    return 255;
}

// horizontal min-plus with sound early exit: d2 = min_jp (j-jp)^2 + g[jp]^2
__device__ __forceinline__ int hmin(const unsigned char* g, int rowbase, int j) {
    int g0 = g[rowbase + j];
    int best = g0 * g0;
    #pragma unroll 1
    for (int r = 1; r < WW; r++) {
        int rr = r * r;
        if (rr >= best) break;                  // sound: farther jp can't win
        if (j - r >= 0) { int a = g[rowbase + j - r]; best = min(best, rr + a*a); }
        if (j + r < WW) { int a = g[rowbase + j + r]; best = min(best, rr + a*a); }
    }
    return best;
}

__global__ __launch_bounds__(NTHR, 1)
void k_all(const float* __restrict__ outp, const int* __restrict__ tgt,
           float* __restrict__ out) {
    __shared__ unsigned char labP[HW];
    __shared__ unsigned char labT[HW];
    __shared__ unsigned char gP[HW];
    __shared__ unsigned char gT[HW];
    __shared__ unsigned mP[NWRD];
    __shared__ unsigned mT[NWRD];
    __shared__ int redF[NWARP], redB[NWARP];

    const int b   = blockIdx.x;
    const int tid = threadIdx.x;
    const int wid = tid >> 5;
    const int lid = tid & 31;

    // ---- phase 1: argmax over channels + target labels -> smem ----
    const float* base = outp + (size_t)b * CC * HW;
    const int*   tb   = tgt + (size_t)b * HW;
    #pragma unroll
    for (int it = 0; it < HW/NTHR; it++) {
        int idx = it * NTHR + tid;
        float v0 = base[idx];
        float v1 = base[idx + HW];
        float v2 = base[idx + 2*HW];
        float v3 = base[idx + 3*HW];
        int bi = 0; float best = v0;
        if (v1 > best) { best = v1; bi = 1; }
        if (v2 > best) { best = v2; bi = 2; }
        if (v3 > best) { best = v3; bi = 3; }
        labP[idx] = (unsigned char)bi;
        labT[idx] = (unsigned char)tb[idx];
    }
    __syncthreads();

    // ---- phase 2: boundary masks, bit-packed via ballot ----
    // warp w lanes cover consecutive idx -> ballot builds one 32-bit word
    #pragma unroll
    for (int it = 0; it < HW/NTHR; it++) {
        int idx = it * NTHR + tid;
        int i = idx / WW, j = idx - i*WW;

        int lp = labP[idx];
        int mp = 0;
        if (i > 0    && labP[idx - WW] != lp) mp = 1;
        if (i < HH-1 && labP[idx + WW] != lp) mp = 1;
        if (j > 0    && labP[idx - 1 ] != lp) mp = 1;
        if (j < WW-1 && labP[idx + 1 ] != lp) mp = 1;

        int lt = labT[idx];
        int mt = 0;
        if (i > 0    && labT[idx - WW] != lt) mt = 1;
        if (i < HH-1 && labT[idx + WW] != lt) mt = 1;
        if (j > 0    && labT[idx - 1 ] != lt) mt = 1;
        if (j < WW-1 && labT[idx + 1 ] != lt) mt = 1;

        unsigned wp = __ballot_sync(0xFFFFFFFFu, mp);
        unsigned wt = __ballot_sync(0xFFFFFFFFu, mt);
        if (lid == 0) {
            int word = idx >> 5;       // = it*24 + wid
            mP[word] = wp;
            mT[word] = wt;
        }
    }
    __syncthreads();

    // ---- phase 3: vertical EDT via outward search (dense masks -> ~1 iter) ----
    #pragma unroll
    for (int it = 0; it < HW/NTHR; it++) {
        int idx = it * NTHR + tid;
        int i = idx / WW;
        gP[idx] = (unsigned char)vsearch(mP, idx, i);
        gT[idx] = (unsigned char)vsearch(mT, idx, i);
    }
    __syncthreads();

    // ---- phase 4: horizontal min-plus + directed-Hausdorff local max ----
    int maxF = -1, maxB = -1;
    #pragma unroll
    for (int it = 0; it < HW/NTHR; it++) {
        int idx = it * NTHR + tid;
        int i = idx / WW, j = idx - i*WW;
        int rowbase = i * WW;
        if (getbit(mP, idx)) {                 // pred boundary -> dist to target set
            int d2 = hmin(gT, rowbase, j);
            maxF = max(maxF, d2);
        }
        if (getbit(mT, idx)) {                 // target boundary -> dist to pred set
            int d2 = hmin(gP, rowbase, j);
            maxB = max(maxB, d2);
        }
    }

    // ---- phase 5: block reduction (block == image) ----
    #pragma unroll
    for (int s = 16; s > 0; s >>= 1) {
        maxF = max(maxF, __shfl_xor_sync(0xFFFFFFFFu, maxF, s));
        maxB = max(maxB, __shfl_xor_sync(0xFFFFFFFFu, maxB, s));
    }
    if (lid == 0) { redF[wid] = maxF; redB[wid] = maxB; }
    __syncthreads();

    if (tid == 0) {
        int f = -1, w = -1;
        #pragma unroll
        for (int k = 0; k < NWARP; k++) { f = max(f, redF[k]); w = max(w, redB[k]); }
        int v = max(max(f, w), 0);
        // empty boundary set -> sentinel >= 65025 >> real max 18050
        float d2 = (v >= 50000) ? 1e10f : (float)v;
        g_res[b] = sqrtf(d2);
        __threadfence();
        unsigned ticket = atomicAdd(&g_count, 1u);
        if (ticket == BB - 1) {
            __threadfence();
            float sum = 0.0f;
            #pragma unroll
            for (int bb = 0; bb < BB; bb++) sum += g_res[bb];
            out[0] = sum * (1.0f / BB);
            g_count = 0;               // reset for next graph replay
        }
    }
}

extern "C" void kernel_launch(void* const* d_in, const int* in_sizes, int n_in,
                              void* d_out, int out_size) {
    const float* outp = (const float*)d_in[0];   // [B,C,H,W] fp32
    const int*   tgt  = (const int*)d_in[1];     // [B,H,W] int32
    k_all<<<BB, NTHR>>>(outp, tgt, (float*)d_out);
}

// round 4
// speedup vs baseline: 3.0775x; 1.1775x over previous
#include <cuda_runtime.h>

#define BB 4
#define CC 4
#define HH 96
#define WW 96
#define HW (HH*WW)
#define NSL 12            // slices per image
#define SR 8              // rows per slice
#define NTHR 768
#define NWARP (NTHR/32)

// column-packed boundary bytes: [b][col][slice] with 16B col stride (u32-aligned)
__device__ unsigned char g_cbP[BB*WW*16];
__device__ unsigned char g_cbT[BB*WW*16];
__device__ unsigned int  g_cnt[BB];       // zero at load; owner resets each launch
__device__ volatile float g_res[BB];
__device__ unsigned int  g_tick;          // zero at load; last owner resets

// nearest set bit distance in a 96-bit column (3 u32 words) from row i; 255 if none
__device__ __forceinline__ int vdist(const unsigned* w, int i) {
    int wi = i >> 5, bit = i & 31;
    int down = 255;
    unsigned r = w[wi] >> bit;
    if (r) down = __ffs(r) - 1;
    else {
        int base = 32 - bit;
        #pragma unroll
        for (int k = 1; k < 3; k++) {
            if (wi + k < 3) {
                unsigned x = w[wi + k];
                if (x) { down = base + __ffs(x) - 1; break; }
                base += 32;
            }
        }
    }
    int up = 255;
    unsigned v = w[wi] << (31 - bit);
    if (v) up = __clz(v);
    else {
        int base = bit + 1;
        #pragma unroll
        for (int k = 1; k < 3; k++) {
            if (wi - k >= 0) {
                unsigned x = w[wi - k];
                if (x) { up = base + __clz(x); break; }
                base += 32;
            }
        }
    }
    return min(min(down, up), 255);
}

// horizontal min-plus with sound early exit: d2 = min_jp (j-jp)^2 + g[jp]^2
__device__ __forceinline__ int hmin(const unsigned char* g, int rowbase, int j) {
    int g0 = g[rowbase + j];
    int best = g0 * g0;
    #pragma unroll 1
    for (int r = 1; r < WW; r++) {
        int rr = r * r;
        if (rr >= best) break;
        if (j - r >= 0) { int a = g[rowbase + j - r]; best = min(best, rr + a*a); }
        if (j + r < WW) { int a = g[rowbase + j + r]; best = min(best, rr + a*a); }
    }
    return best;
}

__global__ __launch_bounds__(NTHR, 1)
void k_all(const float* __restrict__ outp, const int* __restrict__ tgt,
           float* __restrict__ out) {
    __shared__ unsigned char labP[10*WW];
    __shared__ unsigned char labT[10*WW];
    __shared__ unsigned char m8P[SR*WW];
    __shared__ unsigned char m8T[SR*WW];
    __shared__ unsigned char gP[HW];
    __shared__ unsigned char gT[HW];
    __shared__ unsigned cmP[WW*3];
    __shared__ unsigned cmT[WW*3];
    __shared__ int redF[NWARP], redB[NWARP];

    const int bb  = blockIdx.x;
    const int b   = bb / NSL;
    const int s   = bb % NSL;
    const int tid = threadIdx.x;

    // ===== front-end (all 48 blocks): argmax + labels for rows rbase..rbase+9 =====
    const int rbase = s*SR - 1;
    const float* basep = outp + (size_t)b * CC * HW;
    const int*   tb    = tgt + (size_t)b * HW;
    #pragma unroll 2
    for (int p = tid; p < 10*WW; p += NTHR) {
        int li = p / WW, j = p - li*WW;
        int gi = rbase + li;
        if (gi < 0 || gi >= HH) continue;
        int idx = gi*WW + j;
        float v0 = basep[idx];
        float v1 = basep[idx + HW];
        float v2 = basep[idx + 2*HW];
        float v3 = basep[idx + 3*HW];
        int c = 0; float bst = v0;
        if (v1 > bst) { bst = v1; c = 1; }
        if (v2 > bst) { bst = v2; c = 2; }
        if (v3 > bst) { bst = v3; c = 3; }
        labP[p] = (unsigned char)c;
        labT[p] = (unsigned char)tb[idx];
    }
    __syncthreads();

    // ===== boundary for owned SR rows =====
    for (int p = tid; p < SR*WW; p += NTHR) {
        int r = p / WW, j = p - r*WW;
        int gi = s*SR + r;
        int o = (r + 1)*WW + j;          // local row = gi - rbase = r+1
        int lp = labP[o], lt = labT[o];
        int mp = 0, mt = 0;
        if (gi > 0)    { mp |= labP[o-WW] != lp; mt |= labT[o-WW] != lt; }
        if (gi < HH-1) { mp |= labP[o+WW] != lp; mt |= labT[o+WW] != lt; }
        if (j > 0)     { mp |= labP[o-1]  != lp; mt |= labT[o-1]  != lt; }
        if (j < WW-1)  { mp |= labP[o+1]  != lp; mt |= labT[o+1]  != lt; }
        m8P[p] = (unsigned char)mp;
        m8T[p] = (unsigned char)mt;
    }
    __syncthreads();

    // ===== pack 8 row-bits per column, publish to global =====
    if (tid < WW) {
        int bp = 0, bt = 0;
        #pragma unroll
        for (int r = 0; r < SR; r++) {
            bp |= m8P[r*WW + tid] << r;
            bt |= m8T[r*WW + tid] << r;
        }
        g_cbP[(b*WW + tid)*16 + s] = (unsigned char)bp;
        g_cbT[(b*WW + tid)*16 + s] = (unsigned char)bt;
    }
    __syncthreads();
    if (tid == 0) {
        __threadfence();
        atomicAdd(&g_cnt[b], 1u);
    }

    if (s != 0) return;                  // non-owner blocks done

    // ===== owner: wait for all 12 slices of this image =====
    if (tid == 0) {
        while (atomicAdd(&g_cnt[b], 0u) < NSL) { }
        g_cnt[b] = 0;                    // reset for next graph replay
        __threadfence();
    }
    __syncthreads();

    // ===== assemble 96-bit column masks in smem =====
    if (tid < WW) {
        const unsigned* p4 = (const unsigned*)(g_cbP + (b*WW + tid)*16);
        const unsigned* t4 = (const unsigned*)(g_cbT + (b*WW + tid)*16);
        cmP[tid*3+0] = p4[0]; cmP[tid*3+1] = p4[1]; cmP[tid*3+2] = p4[2];
        cmT[tid*3+0] = t4[0]; cmT[tid*3+1] = t4[1]; cmT[tid*3+2] = t4[2];
    }
    __syncthreads();

    // ===== vertical EDT via bit search (g==0 <=> boundary pixel) =====
    #pragma unroll
    for (int it = 0; it < HW/NTHR; it++) {
        int idx = it*NTHR + tid;
        int i = idx / WW, j = idx - i*WW;
        gP[idx] = (unsigned char)vdist(&cmP[j*3], i);
        gT[idx] = (unsigned char)vdist(&cmT[j*3], i);
    }
    __syncthreads();

    // ===== horizontal min-plus + directed Hausdorff max =====
    int maxF = -1, maxB = -1;
    #pragma unroll
    for (int it = 0; it < HW/NTHR; it++) {
        int idx = it*NTHR + tid;
        int i = idx / WW, j = idx - i*WW;
        int rowbase = i*WW;
        if (gP[idx] == 0) maxF = max(maxF, hmin(gT, rowbase, j));  // pred -> tgt set
        if (gT[idx] == 0) maxB = max(maxB, hmin(gP, rowbase, j));  // tgt -> pred set
    }

    // ===== block reduction (block == image) =====
    #pragma unroll
    for (int sh = 16; sh > 0; sh >>= 1) {
        maxF = max(maxF, __shfl_xor_sync(0xFFFFFFFFu, maxF, sh));
        maxB = max(maxB, __shfl_xor_sync(0xFFFFFFFFu, maxB, sh));
    }
    if ((tid & 31) == 0) { redF[tid >> 5] = maxF; redB[tid >> 5] = maxB; }
    __syncthreads();

    if (tid == 0) {
        int f = -1, w = -1;
        #pragma unroll
        for (int k = 0; k < NWARP; k++) { f = max(f, redF[k]); w = max(w, redB[k]); }
        int v = max(max(f, w), 0);
        // empty-boundary sentinel (>=65025) >> real max 18050
        float d2 = (v >= 50000) ? 1e10f : (float)v;
        g_res[b] = sqrtf(d2);
        __threadfence();
        unsigned ticket = atomicAdd(&g_tick, 1u);
        if (ticket == BB - 1) {
            __threadfence();
            float sum = 0.0f;
            #pragma unroll
            for (int k = 0; k < BB; k++) sum += g_res[k];
            out[0] = sum * (1.0f / BB);
            g_tick = 0;                  // reset for next graph replay
        }
    }
}

extern "C" void kernel_launch(void* const* d_in, const int* in_sizes, int n_in,
                              void* d_out, int out_size) {
    const float* outp = (const float*)d_in[0];   // [B,C,H,W] fp32
    const int*   tgt  = (const int*)d_in[1];     // [B,H,W] int32
    k_all<<<BB*NSL, NTHR>>>(outp, tgt, (float*)d_out);
}

// round 5
// speedup vs baseline: 3.4579x; 1.1236x over previous
#include <cuda_runtime.h>

#define BB 4
#define CC 4
#define HH 96
#define WW 96
#define HW (HH*WW)
#define NSL 12            // slices per image
#define SR 8              // rows per slice
#define NTHR 768
#define NWARP (NTHR/32)
#define NBLK (BB*NSL)

// column-packed boundary bytes: [b][col] -> 16B slot (12 slice bytes used)
__device__ unsigned char g_cbP[BB*WW*16];
__device__ unsigned char g_cbT[BB*WW*16];
__device__ unsigned int  g_cnt[BB];       // slice arrival counter (zero at load)
__device__ unsigned int  g_done[BB];      // barrier exit counter
__device__ int g_fwd[BB];                 // per-image directed max (>=0)
__device__ int g_bwd[BB];
__device__ unsigned int  g_tick;          // final-reduction ticket

// nearest set bit distance in a 96-bit column (3 u32 words) from row i; 255 if none
__device__ __forceinline__ int vdist(unsigned w0, unsigned w1, unsigned w2, int i) {
    unsigned w[3] = {w0, w1, w2};
    int wi = i >> 5, bit = i & 31;
    int down = 255;
    unsigned r = w[wi] >> bit;
    if (r) down = __ffs(r) - 1;
    else {
        int base = 32 - bit;
        #pragma unroll
        for (int k = 1; k < 3; k++) {
            if (wi + k < 3) {
                unsigned x = w[wi + k];
                if (x) { down = base + __ffs(x) - 1; break; }
                base += 32;
            }
        }
    }
    int up = 255;
    unsigned v = w[wi] << (31 - bit);
    if (v) up = __clz(v);
    else {
        int base = bit + 1;
        #pragma unroll
        for (int k = 1; k < 3; k++) {
            if (wi - k >= 0) {
                unsigned x = w[wi - k];
                if (x) { up = base + __clz(x); break; }
                base += 32;
            }
        }
    }
    return min(min(down, up), 255);
}

// horizontal min-plus with sound early exit: d2 = min_jp (j-jp)^2 + g[jp]^2
__device__ __forceinline__ int hmin(const unsigned char* g, int j) {
    int g0 = g[j];
    int best = g0 * g0;
    #pragma unroll 1
    for (int r = 1; r < WW; r++) {
        int rr = r * r;
        if (rr >= best) break;
        if (j - r >= 0) { int a = g[j - r]; best = min(best, rr + a*a); }
        if (j + r < WW) { int a = g[j + r]; best = min(best, rr + a*a); }
    }
    return best;
}

__global__ __launch_bounds__(NTHR, 1)
void k_all(const float* __restrict__ outp, const int* __restrict__ tgt,
           float* __restrict__ out) {
    __shared__ unsigned char labP[10*WW];
    __shared__ unsigned char labT[10*WW];
    __shared__ unsigned char m8P[SR*WW];
    __shared__ unsigned char m8T[SR*WW];
    __shared__ unsigned cmP[WW*3];
    __shared__ unsigned cmT[WW*3];
    __shared__ unsigned char gPr[SR*WW];
    __shared__ unsigned char gTr[SR*WW];
    __shared__ int redF[NWARP], redB[NWARP];

    const int bb  = blockIdx.x;
    const int b   = bb / NSL;
    const int s   = bb % NSL;
    const int tid = threadIdx.x;

    // ===== phase A: argmax + labels for rows rbase..rbase+9 (halo) =====
    const int rbase = s*SR - 1;
    const float* basep = outp + (size_t)b * CC * HW;
    const int*   tb    = tgt + (size_t)b * HW;
    #pragma unroll 2
    for (int p = tid; p < 10*WW; p += NTHR) {
        int li = p / WW, j = p - li*WW;
        int gi = rbase + li;
        if (gi < 0 || gi >= HH) continue;
        int idx = gi*WW + j;
        float v0 = basep[idx];
        float v1 = basep[idx + HW];
        float v2 = basep[idx + 2*HW];
        float v3 = basep[idx + 3*HW];
        int c = 0; float bst = v0;
        if (v1 > bst) { bst = v1; c = 1; }
        if (v2 > bst) { bst = v2; c = 2; }
        if (v3 > bst) { bst = v3; c = 3; }
        labP[p] = (unsigned char)c;
        labT[p] = (unsigned char)tb[idx];
    }
    __syncthreads();

    // ===== boundary for owned SR rows =====
    for (int p = tid; p < SR*WW; p += NTHR) {
        int r = p / WW, j = p - r*WW;
        int gi = s*SR + r;
        int o = (r + 1)*WW + j;
        int lp = labP[o], lt = labT[o];
        int mp = 0, mt = 0;
        if (gi > 0)    { mp |= labP[o-WW] != lp; mt |= labT[o-WW] != lt; }
        if (gi < HH-1) { mp |= labP[o+WW] != lp; mt |= labT[o+WW] != lt; }
        if (j > 0)     { mp |= labP[o-1]  != lp; mt |= labT[o-1]  != lt; }
        if (j < WW-1)  { mp |= labP[o+1]  != lp; mt |= labT[o+1]  != lt; }
        m8P[p] = (unsigned char)mp;
        m8T[p] = (unsigned char)mt;
    }
    __syncthreads();

    // ===== pack 8 row-bits per column, publish =====
    if (tid < WW) {
        int bp = 0, bt = 0;
        #pragma unroll
        for (int r = 0; r < SR; r++) {
            bp |= m8P[r*WW + tid] << r;
            bt |= m8T[r*WW + tid] << r;
        }
        g_cbP[(b*WW + tid)*16 + s] = (unsigned char)bp;
        g_cbT[(b*WW + tid)*16 + s] = (unsigned char)bt;
    }
    __syncthreads();

    // ===== per-image barrier (all 48 blocks co-resident -> no deadlock) =====
    if (tid == 0) {
        __threadfence();
        atomicAdd(&g_cnt[b], 1u);
        while (atomicAdd(&g_cnt[b], 0u) < NSL) { }
        __threadfence();
        unsigned d = atomicAdd(&g_done[b], 1u);
        if (d == NSL - 1) { g_cnt[b] = 0; g_done[b] = 0; }   // safe: all have passed
    }
    __syncthreads();

    // ===== phase B (all blocks): load column masks =====
    if (tid < WW) {
        uint4 p4 = *(const uint4*)(g_cbP + (b*WW + tid)*16);
        uint4 t4 = *(const uint4*)(g_cbT + (b*WW + tid)*16);
        cmP[tid*3+0] = p4.x; cmP[tid*3+1] = p4.y; cmP[tid*3+2] = p4.z;
        cmT[tid*3+0] = t4.x; cmT[tid*3+1] = t4.y; cmT[tid*3+2] = t4.z;
    }
    __syncthreads();

    // ===== vertical EDT for own 8 rows (g==0 <=> boundary) =====
    {
        int p = tid;                      // SR*WW == NTHR: one pixel per thread
        int r = p / WW, j = p - r*WW;
        int i = s*SR + r;
        gPr[p] = (unsigned char)vdist(cmP[j*3], cmP[j*3+1], cmP[j*3+2], i);
        gTr[p] = (unsigned char)vdist(cmT[j*3], cmT[j*3+1], cmT[j*3+2], i);
    }
    __syncthreads();

    // ===== horizontal min-plus + directed max over own rows =====
    int maxF = -1, maxB = -1;
    {
        int p = tid;
        int r = p / WW, j = p - r*WW;
        const unsigned char* gTrow = gTr + r*WW;
        const unsigned char* gProw = gPr + r*WW;
        if (gPr[p] == 0) maxF = hmin(gTrow, j);   // pred boundary -> target set
        if (gTr[p] == 0) maxB = hmin(gProw, j);   // target boundary -> pred set
    }

    // ===== block reduction, then per-image atomicMax =====
    #pragma unroll
    for (int sh = 16; sh > 0; sh >>= 1) {
        maxF = max(maxF, __shfl_xor_sync(0xFFFFFFFFu, maxF, sh));
        maxB = max(maxB, __shfl_xor_sync(0xFFFFFFFFu, maxB, sh));
    }
    if ((tid & 31) == 0) { redF[tid >> 5] = maxF; redB[tid >> 5] = maxB; }
    __syncthreads();

    if (tid == 0) {
        int f = -1, w = -1;
        #pragma unroll
        for (int k = 0; k < NWARP; k++) { f = max(f, redF[k]); w = max(w, redB[k]); }
        if (f > 0) atomicMax(&g_fwd[b], f);
        if (w > 0) atomicMax(&g_bwd[b], w);
        __threadfence();
        unsigned ticket = atomicAdd(&g_tick, 1u);
        if (ticket == NBLK - 1) {
            __threadfence();
            float sum = 0.0f;
            #pragma unroll
            for (int k = 0; k < BB; k++) {
                int v = max(max(g_fwd[k], g_bwd[k]), 0);
                float d2 = (v >= 50000) ? 1e10f : (float)v;   // empty-set sentinel
                sum += sqrtf(d2);
            }
            out[0] = sum * (1.0f / BB);
            #pragma unroll
            for (int k = 0; k < BB; k++) { g_fwd[k] = 0; g_bwd[k] = 0; }
            g_tick = 0;
        }
    }
}

extern "C" void kernel_launch(void* const* d_in, const int* in_sizes, int n_in,
                              void* d_out, int out_size) {
    const float* outp = (const float*)d_in[0];   // [B,C,H,W] fp32
    const int*   tgt  = (const int*)d_in[1];     // [B,H,W] int32
    k_all<<<NBLK, NTHR>>>(outp, tgt, (float*)d_out);
}

// round 6
// speedup vs baseline: 4.3498x; 1.2580x over previous
#include <cuda_runtime.h>
#include <cstdint>

#define BB 4
#define CC 4
#define HH 96
#define WW 96
#define HW (HH*WW)
#define CSZ 8             // cluster size = slices per image
#define SR 12             // rows per slice
#define NTHR 768
#define NWARP (NTHR/32)
#define NBLK (BB*CSZ)

__device__ int g_fwd[BB];        // zero at load; last ticket resets
__device__ int g_bwd[BB];
__device__ volatile float g_resv[BB];
__device__ unsigned g_tick;

#define CLUSTER_SYNC() do { \
    asm volatile("barrier.cluster.arrive.aligned;" ::: "memory"); \
    asm volatile("barrier.cluster.wait.aligned;" ::: "memory"); } while (0)

__device__ __forceinline__ unsigned smem_u32(const void* p) {
    unsigned a;
    asm("{ .reg .u64 t; cvta.to.shared.u64 t, %1; cvt.u32.u64 %0, t; }"
        : "=r"(a) : "l"(p));
    return a;
}
__device__ __forceinline__ unsigned cluster_rank() {
    unsigned r; asm("mov.u32 %0, %%cluster_ctarank;" : "=r"(r)); return r;
}
__device__ __forceinline__ unsigned ld_cluster_u32(unsigned local_addr, unsigned rank) {
    unsigned ra, v;
    asm("mapa.shared::cluster.u32 %0, %1, %2;" : "=r"(ra) : "r"(local_addr), "r"(rank));
    asm("ld.shared::cluster.u32 %0, [%1];" : "=r"(v) : "r"(ra));
    return v;
}

// nearest set bit distance in a 96-bit column (3 u32 words) from row i; 255 if none
__device__ __forceinline__ int vdist(unsigned w0, unsigned w1, unsigned w2, int i) {
    unsigned w[3] = {w0, w1, w2};
    int wi = i >> 5, bit = i & 31;
    int down = 255;
    unsigned r = w[wi] >> bit;
    if (r) down = __ffs(r) - 1;
    else {
        int base = 32 - bit;
        #pragma unroll
        for (int k = 1; k < 3; k++) {
            if (wi + k < 3) {
                unsigned x = w[wi + k];
                if (x) { down = base + __ffs(x) - 1; break; }
                base += 32;
            }
        }
    }
    int up = 255;
    unsigned v = w[wi] << (31 - bit);
    if (v) up = __clz(v);
    else {
        int base = bit + 1;
        #pragma unroll
        for (int k = 1; k < 3; k++) {
            if (wi - k >= 0) {
                unsigned x = w[wi - k];
                if (x) { up = base + __clz(x); break; }
                base += 32;
            }
        }
    }
    return min(min(down, up), 255);
}

// horizontal min-plus with sound early exit: d2 = min_jp (j-jp)^2 + g[jp]^2
__device__ __forceinline__ int hmin(const unsigned char* g, int j) {
    int g0 = g[j];
    int best = g0 * g0;
    #pragma unroll 1
    for (int r = 1; r < WW; r++) {
        int rr = r * r;
        if (rr >= best) break;
        if (j - r >= 0) { int a = g[j - r]; best = min(best, rr + a*a); }
        if (j + r < WW) { int a = g[j + r]; best = min(best, rr + a*a); }
    }
    return best;
}

__device__ __forceinline__ int amax4(float v0, float v1, float v2, float v3) {
    int c = 0; float b = v0;
    if (v1 > b) { b = v1; c = 1; }
    if (v2 > b) { b = v2; c = 2; }
    if (v3 > b) { b = v3; c = 3; }
    return c;
}

__global__ __launch_bounds__(NTHR, 1) __cluster_dims__(CSZ, 1, 1)
void k_all(const float* __restrict__ outp, const int* __restrict__ tgt,
           float* __restrict__ out) {
    __shared__ unsigned char labP[(SR+2)*WW];
    __shared__ unsigned char labT[(SR+2)*WW];
    __shared__ unsigned char m12P[SR*WW];
    __shared__ unsigned char m12T[SR*WW];
    __shared__ unsigned cmLoc[WW];          // per-column 12-bit chunks: P lo16, T hi16
    __shared__ unsigned cmP[WW*3];
    __shared__ unsigned cmT[WW*3];
    __shared__ unsigned char gPr[SR*WW];
    __shared__ unsigned char gTr[SR*WW];
    __shared__ int redF[NWARP], redB[NWARP];

    const int bb  = blockIdx.x;
    const int b   = bb / CSZ;
    const int s   = cluster_rank();          // slice within image
    const int tid = threadIdx.x;

    // ===== phase A: float4 argmax + labels for rows rbase..rbase+13 (halo) =====
    const int rbase = s*SR - 1;
    const float* basep = outp + (size_t)b * CC * HW;
    const int*   tb    = tgt + (size_t)b * HW;
    if (tid < (SR+2) * (WW/4)) {             // 14 rows * 24 float4 groups = 336
        int li = tid / (WW/4), jv = tid % (WW/4);
        int gi = rbase + li;
        if (gi >= 0 && gi < HH) {
            int idx = gi*WW + jv*4;
            float4 a0 = *(const float4*)(basep + idx);
            float4 a1 = *(const float4*)(basep + idx + HW);
            float4 a2 = *(const float4*)(basep + idx + 2*HW);
            float4 a3 = *(const float4*)(basep + idx + 3*HW);
            int4  t4  = *(const int4*)(tb + idx);
            unsigned lp = (unsigned)amax4(a0.x, a1.x, a2.x, a3.x)
                        | ((unsigned)amax4(a0.y, a1.y, a2.y, a3.y) << 8)
                        | ((unsigned)amax4(a0.z, a1.z, a2.z, a3.z) << 16)
                        | ((unsigned)amax4(a0.w, a1.w, a2.w, a3.w) << 24);
            unsigned lt = (unsigned)t4.x | ((unsigned)t4.y << 8)
                        | ((unsigned)t4.z << 16) | ((unsigned)t4.w << 24);
            *(unsigned*)&labP[li*WW + jv*4] = lp;
            *(unsigned*)&labT[li*WW + jv*4] = lt;
        }
    }
    __syncthreads();

    // ===== boundary for owned SR rows =====
    for (int p = tid; p < SR*WW; p += NTHR) {
        int r = p / WW, j = p - r*WW;
        int gi = s*SR + r;
        int o = (r + 1)*WW + j;
        int lp = labP[o], lt = labT[o];
        int mp = 0, mt = 0;
        if (gi > 0)    { mp |= labP[o-WW] != lp; mt |= labT[o-WW] != lt; }
        if (gi < HH-1) { mp |= labP[o+WW] != lp; mt |= labT[o+WW] != lt; }
        if (j > 0)     { mp |= labP[o-1]  != lp; mt |= labT[o-1]  != lt; }
        if (j < WW-1)  { mp |= labP[o+1]  != lp; mt |= labT[o+1]  != lt; }
        m12P[p] = (unsigned char)mp;
        m12T[p] = (unsigned char)mt;
    }
    __syncthreads();

    // ===== pack 12 row-bits per column into local smem chunk =====
    if (tid < WW) {
        unsigned cp = 0, ct = 0;
        #pragma unroll
        for (int r = 0; r < SR; r++) {
            cp |= (unsigned)m12P[r*WW + tid] << r;
            ct |= (unsigned)m12T[r*WW + tid] << r;
        }
        cmLoc[tid] = cp | (ct << 16);
    }
    __syncthreads();

    // ===== cluster barrier: all 8 slices' chunks visible =====
    CLUSTER_SYNC();

    // ===== assemble full 96-bit column masks via DSMEM =====
    if (tid < WW) {
        unsigned addr = smem_u32(&cmLoc[tid]);
        unsigned long long loP = 0, loT = 0;
        unsigned hiP = 0, hiT = 0;
        #pragma unroll
        for (int k = 0; k < CSZ; k++) {
            unsigned v = ld_cluster_u32(addr, (unsigned)k);
            unsigned cp = v & 0xFFFu;
            unsigned ct = (v >> 16) & 0xFFFu;
            const int pos = 12 * k;
            if (pos < 64) {
                loP |= (unsigned long long)cp << pos;
                loT |= (unsigned long long)ct << pos;
                if (pos > 52) {                  // k == 5: bits spill into hi
                    hiP |= cp >> (64 - pos);
                    hiT |= ct >> (64 - pos);
                }
            } else {
                hiP |= cp << (pos - 64);
                hiT |= ct << (pos - 64);
            }
        }
        cmP[tid*3+0] = (unsigned)loP;
        cmP[tid*3+1] = (unsigned)(loP >> 32);
        cmP[tid*3+2] = hiP;
        cmT[tid*3+0] = (unsigned)loT;
        cmT[tid*3+1] = (unsigned)(loT >> 32);
        cmT[tid*3+2] = hiT;
    }
    __syncthreads();

    // ===== cluster barrier #2: all DSMEM reads done before any CTA may exit =====
    CLUSTER_SYNC();

    // ===== vertical EDT for own 12 rows (g==0 <=> boundary) =====
    for (int p = tid; p < SR*WW; p += NTHR) {
        int r = p / WW, j = p - r*WW;
        int i = s*SR + r;
        gPr[p] = (unsigned char)vdist(cmP[j*3], cmP[j*3+1], cmP[j*3+2], i);
        gTr[p] = (unsigned char)vdist(cmT[j*3], cmT[j*3+1], cmT[j*3+2], i);
    }
    __syncthreads();

    // ===== horizontal min-plus + directed max over own rows =====
    int maxF = -1, maxB = -1;
    for (int p = tid; p < SR*WW; p += NTHR) {
        int r = p / WW, j = p - r*WW;
        if (gPr[p] == 0) maxF = max(maxF, hmin(gTr + r*WW, j));  // pred -> tgt
        if (gTr[p] == 0) maxB = max(maxB, hmin(gPr + r*WW, j));  // tgt -> pred
    }

    // ===== block reduction, per-image atomicMax, final ticket =====
    #pragma unroll
    for (int sh = 16; sh > 0; sh >>= 1) {
        maxF = max(maxF, __shfl_xor_sync(0xFFFFFFFFu, maxF, sh));
        maxB = max(maxB, __shfl_xor_sync(0xFFFFFFFFu, maxB, sh));
    }
    if ((tid & 31) == 0) { redF[tid >> 5] = maxF; redB[tid >> 5] = maxB; }
    __syncthreads();

    if (tid == 0) {
        int f = -1, w = -1;
        #pragma unroll
        for (int k = 0; k < NWARP; k++) { f = max(f, redF[k]); w = max(w, redB[k]); }
        if (f > 0) atomicMax(&g_fwd[b], f);
        if (w > 0) atomicMax(&g_bwd[b], w);
        __threadfence();
        unsigned ticket = atomicAdd(&g_tick, 1u);
        if (ticket == NBLK - 1) {
            __threadfence();
            float sum = 0.0f;
            #pragma unroll
            for (int k = 0; k < BB; k++) {
                int v = max(max(g_fwd[k], g_bwd[k]), 0);
                float d2 = (v >= 50000) ? 1e10f : (float)v;   // empty-set sentinel
                sum += sqrtf(d2);
            }
            out[0] = sum * (1.0f / BB);
            #pragma unroll
            for (int k = 0; k < BB; k++) { g_fwd[k] = 0; g_bwd[k] = 0; }
            g_tick = 0;
        }
    }
}

extern "C" void kernel_launch(void* const* d_in, const int* in_sizes, int n_in,
                              void* d_out, int out_size) {
    const float* outp = (const float*)d_in[0];   // [B,C,H,W] fp32
    const int*   tgt  = (const int*)d_in[1];     // [B,H,W] int32
    k_all<<<NBLK, NTHR>>>(outp, tgt, (float*)d_out);
}